// round 3
// baseline (speedup 1.0000x reference)
#include <cuda_runtime.h>
#include <math.h>

#define B_  4
#define C_  64
#define T_  128
#define Fd_ 128
#define H_  128
#define K_  8
#define L_  121              // F - K + 1
#define N_  (B_*T_)          // 512
#define M_  (L_*N_)          // 61952
#define CK_ (C_*K_)          // 512

// ---- scratch (device globals; no allocation allowed) ----
__device__ float g_xn[B_*C_*T_*Fd_];     //  16.8 MB  normed input
__device__ float g_h0[M_*CK_];           // 126.9 MB  unfolded layer-0 input
__device__ float g_h [M_*2*H_];          //  63.4 MB  layer output (ping)
__device__ float g_U [M_*8*H_];          // 253.8 MB  GEMM output (z,f,r,hp x 2 dirs)

// ---------------- channel norm over C ----------------
__global__ void knorm(const float* __restrict__ x, const float* __restrict__ gamma,
                      const float* __restrict__ beta) {
    int idx = blockIdx.x * blockDim.x + threadIdx.x;   // over B*T*F
    if (idx >= B_*T_*Fd_) return;
    int f = idx % Fd_;
    int t = (idx / Fd_) % T_;
    int b = idx / (T_*Fd_);
    float v[C_];
    float s = 0.f;
#pragma unroll
    for (int c = 0; c < C_; ++c) {
        v[c] = x[((b*C_ + c)*T_ + t)*Fd_ + f];
        s += v[c];
    }
    float mu = s * (1.0f/C_);
    float vs = 0.f;
#pragma unroll
    for (int c = 0; c < C_; ++c) { float d = v[c]-mu; vs += d*d; }
    float inv = rsqrtf(vs*(1.0f/C_) + 1e-8f);
#pragma unroll
    for (int c = 0; c < C_; ++c) {
        g_xn[((b*C_ + c)*T_ + t)*Fd_ + f] = gamma[c]*(v[c]-mu)*inv + beta[c];
    }
}

// ---------------- unfold: h0[l][n][c*K+k] = xn[b][c][t][l+k] ----------------
__global__ void kunfold() {
    int idx = blockIdx.x * blockDim.x + threadIdx.x;   // over M_*CK_
    if (idx >= M_*CK_) return;
    int ck = idx & 511;
    int m  = idx >> 9;
    int n  = m % N_;
    int l  = m / N_;
    int c  = ck >> 3, k = ck & 7;
    int b  = n >> 7, t = n & 127;
    g_h0[idx] = g_xn[((b*C_ + c)*T_ + t)*Fd_ + (l + k)];
}

// ---------------- fp32 SGEMM: C = A(MxK) * B(KxN), row-major, dims % tile == 0 ----------------
__global__ __launch_bounds__(256) void sgemm(const float* __restrict__ A,
                                             const float* __restrict__ Bm,
                                             float* __restrict__ Cm,
                                             int M, int N, int K) {
    __shared__ float As[8][128];
    __shared__ float Bs[8][128];
    int tid  = threadIdx.x;
    int bm   = blockIdx.x * 128;
    int bn   = blockIdx.y * 128;
    int aRow = tid >> 1;
    int aCol = (tid & 1) << 2;
    int bRow = tid >> 5;
    int bCol = (tid & 31) << 2;
    int tr   = (tid >> 4) << 3;
    int tc   = (tid & 15) << 3;

    const float* Ap = A  + (size_t)(bm + aRow) * K + aCol;
    const float* Bp = Bm + (size_t)bRow * N + bn + bCol;

    float acc[8][8];
#pragma unroll
    for (int i = 0; i < 8; ++i)
#pragma unroll
        for (int j = 0; j < 8; ++j) acc[i][j] = 0.f;

    for (int k0 = 0; k0 < K; k0 += 8) {
        float4 av = *(const float4*)(Ap + k0);
        float4 bv = *(const float4*)(Bp + (size_t)k0 * N);
        As[aCol+0][aRow] = av.x;
        As[aCol+1][aRow] = av.y;
        As[aCol+2][aRow] = av.z;
        As[aCol+3][aRow] = av.w;
        *(float4*)&Bs[bRow][bCol] = bv;
        __syncthreads();
#pragma unroll
        for (int kk = 0; kk < 8; ++kk) {
            float a[8], b[8];
            *(float4*)(a)   = *(const float4*)&As[kk][tr];
            *(float4*)(a+4) = *(const float4*)&As[kk][tr+4];
            *(float4*)(b)   = *(const float4*)&Bs[kk][tc];
            *(float4*)(b+4) = *(const float4*)&Bs[kk][tc+4];
#pragma unroll
            for (int i = 0; i < 8; ++i)
#pragma unroll
                for (int j = 0; j < 8; ++j)
                    acc[i][j] += a[i] * b[j];
        }
        __syncthreads();
    }
#pragma unroll
    for (int i = 0; i < 8; ++i) {
        float4 v0 = make_float4(acc[i][0], acc[i][1], acc[i][2], acc[i][3]);
        float4 v1 = make_float4(acc[i][4], acc[i][5], acc[i][6], acc[i][7]);
        size_t off = (size_t)(bm + tr + i) * N + bn + tc;
        *(float4*)&Cm[off]     = v0;
        *(float4*)&Cm[off + 4] = v1;
    }
}

// ---------------- SRU scan + highway (both directions) ----------------
__global__ void kscan(const float* __restrict__ U, float* __restrict__ hout,
                      const float* __restrict__ bf, const float* __restrict__ br) {
    int n   = blockIdx.x;
    int dir = blockIdx.y;
    int h   = threadIdx.x;
    int base = dir * (4*H_) + h;          // column within U row (stride 8H)
    float bfv = bf[dir*H_ + h];
    float brv = br[dir*H_ + h];
    int l    = dir ? (L_ - 1) : 0;
    int step = dir ? -1 : 1;
    float c = 0.f;

    size_t ro = ((size_t)(l * N_ + n)) * (8*H_) + base;
    float z  = U[ro];
    float fv = U[ro + H_];
    float rv = U[ro + 2*H_];
    float hp = U[ro + 3*H_];

    for (int it = 0; it < L_; ++it) {
        int lcur = l;
        int lnext = l + step;
        float zn = 0.f, fn = 0.f, rn = 0.f, hpn = 0.f;
        if (it + 1 < L_) {
            size_t ro2 = ((size_t)(lnext * N_ + n)) * (8*H_) + base;
            zn  = U[ro2];
            fn  = U[ro2 + H_];
            rn  = U[ro2 + 2*H_];
            hpn = U[ro2 + 3*H_];
        }
        float ff = 1.f / (1.f + __expf(-(fv + bfv)));
        float rr = 1.f / (1.f + __expf(-(rv + brv)));
        c = ff * c + (1.f - ff) * z;
        float o = rr * c + (1.f - rr) * hp;
        hout[((size_t)(lcur * N_ + n)) * (2*H_) + dir*H_ + h] = o;
        z = zn; fv = fn; rv = rn; hp = hpn;
        l = lnext;
    }
}

// ---------------- conv-transpose gather + bias + residual ----------------
// Y[m = l*N+n][c*8+k] = (h_final @ convW_flat)  already computed by sgemm.
// out[b][c][t][fo] = xn + convb[c] + sum_k Y[(fo-k)*N + n][c*8+k]  (valid l only)
#define TFO 16
__global__ void kfinal(const float* __restrict__ Y, const float* __restrict__ convb,
                       float* __restrict__ out) {
    __shared__ float sh[23 * 513];
    int n   = blockIdx.x;
    int fob = blockIdx.y * TFO;
    int tid = threadIdx.x;
    for (int i = tid; i < 23 * 512; i += 256) {
        int r = i >> 9, col = i & 511;
        int l = fob - 7 + r;
        float v = 0.f;
        if (l >= 0 && l < L_) v = Y[((size_t)(l * N_ + n)) * 512 + col];
        sh[r * 513 + col] = v;
    }
    __syncthreads();
    int fo_local = tid & 15;
    int cg = tid >> 4;                    // 0..15, each does 4 channels
    int fo = fob + fo_local;
    int b = n >> 7, t = n & 127;
#pragma unroll
    for (int cc = 0; cc < 4; ++cc) {
        int c = cg * 4 + cc;
        float acc = convb[c];
#pragma unroll
        for (int k = 0; k < 8; ++k)
            acc += sh[(fo_local + 7 - k) * 513 + c * 8 + k];
        int oi = ((b*C_ + c)*T_ + t)*Fd_ + fo;
        out[oi] = acc + g_xn[oi];
    }
}

extern "C" void kernel_launch(void* const* d_in, const int* in_sizes, int n_in,
                              void* d_out, int out_size) {
    const float* x     = (const float*)d_in[0];
    const float* gamma = (const float*)d_in[1];
    const float* beta  = (const float*)d_in[2];
    const float* W[4]  = {(const float*)d_in[3],  (const float*)d_in[6],
                          (const float*)d_in[9],  (const float*)d_in[12]};
    const float* bf[4] = {(const float*)d_in[4],  (const float*)d_in[7],
                          (const float*)d_in[10], (const float*)d_in[13]};
    const float* br[4] = {(const float*)d_in[5],  (const float*)d_in[8],
                          (const float*)d_in[11], (const float*)d_in[14]};
    const float* convW = (const float*)d_in[15];   // (2H, C, K) row-major == (256, 512)
    const float* convb = (const float*)d_in[16];
    float* out = (float*)d_out;

    void *pU, *ph0, *ph;
    cudaGetSymbolAddress(&pU,  g_U);
    cudaGetSymbolAddress(&ph0, g_h0);
    cudaGetSymbolAddress(&ph,  g_h);

    knorm<<<(B_*T_*Fd_ + 255)/256, 256>>>(x, gamma, beta);
    kunfold<<<(M_*CK_ + 255)/256, 256>>>();

    // layer 0: A = h0 (M x 512), B = W0 flat (512 x 1024)
    sgemm<<<dim3(M_/128, 8), 256>>>((const float*)ph0, W[0], (float*)pU, M_, 1024, 512);
    kscan<<<dim3(N_, 2), 128>>>((const float*)pU, (float*)ph, bf[0], br[0]);

    for (int i = 1; i < 4; ++i) {
        sgemm<<<dim3(M_/128, 8), 256>>>((const float*)ph, W[i], (float*)pU, M_, 1024, 256);
        kscan<<<dim3(N_, 2), 128>>>((const float*)pU, (float*)ph, bf[i], br[i]);
    }

    // conv-transpose as GEMM: Y (M x 512) = h_final (M x 256) @ convW_flat (256 x 512)
    sgemm<<<dim3(M_/128, 4), 256>>>((const float*)ph, convW, (float*)pU, M_, 512, 256);
    kfinal<<<dim3(N_, Fd_/TFO), 256>>>((const float*)pU, convb, out);
}

// round 6
// speedup vs baseline: 1.9421x; 1.9421x over previous
#include <cuda_runtime.h>
#include <cuda_bf16.h>
#include <math.h>
#include <stdint.h>

#define B_  4
#define C_  64
#define T_  128
#define Fd_ 128
#define H_  128
#define K_  8
#define L_  121              // F - K + 1
#define N_  (B_*T_)          // 512
#define M_  (L_*N_)          // 61952
#define CK_ (C_*K_)          // 512

// weight scratch offsets (elements) for transposed bf16 hi/lo weights [N][K]
#define WOFF0 0
#define WOFF1 (1024*512)
#define WOFF2 (WOFF1 + 1024*256)
#define WOFF3 (WOFF2 + 1024*256)
#define WOFFC (WOFF3 + 1024*256)
#define WTOT  (WOFFC + 512*256)

// ---- scratch (device globals; no allocation allowed) ----
__device__ float         g_xn [B_*C_*T_*Fd_];   // 16.8 MB  normed input (fp32, for residual)
__device__ __nv_bfloat16 g_h0h[M_*CK_];         // 63.4 MB  unfolded input hi
__device__ __nv_bfloat16 g_h0l[M_*CK_];         // 63.4 MB  unfolded input lo
__device__ __nv_bfloat16 g_hh [M_*2*H_];        // 31.7 MB  layer output hi
__device__ __nv_bfloat16 g_hl [M_*2*H_];        // 31.7 MB  layer output lo
__device__ float         g_U  [M_*8*H_];        // 253.8 MB GEMM output (fp32)
__device__ __nv_bfloat16 g_Bth[WTOT];           // transposed weights hi
__device__ __nv_bfloat16 g_Btl[WTOT];           // transposed weights lo

// ============================ helpers ============================
__device__ __forceinline__ uint32_t smem_u32(const void* p) {
    uint32_t a;
    asm("{ .reg .u64 t; cvta.to.shared.u64 t, %1; cvt.u32.u64 %0, t; }" : "=r"(a) : "l"(p));
    return a;
}
__device__ __forceinline__ void cp16(uint32_t s, const void* g) {
    asm volatile("cp.async.cg.shared.global [%0], [%1], 16;" :: "r"(s), "l"(g) : "memory");
}
#define CP_COMMIT() asm volatile("cp.async.commit_group;" ::: "memory")

__device__ __forceinline__ void ldsm4(uint32_t* r, uint32_t addr) {
    asm volatile("ldmatrix.sync.aligned.m8n8.x4.shared.b16 {%0,%1,%2,%3}, [%4];"
        : "=r"(r[0]), "=r"(r[1]), "=r"(r[2]), "=r"(r[3]) : "r"(addr));
}
__device__ __forceinline__ void hmma(float* c, const uint32_t* a, uint32_t b0, uint32_t b1) {
    asm volatile("mma.sync.aligned.m16n8k16.row.col.f32.bf16.bf16.f32 "
        "{%0,%1,%2,%3}, {%4,%5,%6,%7}, {%8,%9}, {%0,%1,%2,%3};"
        : "+f"(c[0]), "+f"(c[1]), "+f"(c[2]), "+f"(c[3])
        : "r"(a[0]), "r"(a[1]), "r"(a[2]), "r"(a[3]), "r"(b0), "r"(b1));
}

__device__ __forceinline__ void split_store(__nv_bfloat16* ph, __nv_bfloat16* pl,
                                            size_t idx, float v) {
    __nv_bfloat16 h = __float2bfloat16(v);
    ph[idx] = h;
    pl[idx] = __float2bfloat16(v - __bfloat162float(h));
}

// ============================ channel norm ============================
__global__ void knorm(const float* __restrict__ x, const float* __restrict__ gamma,
                      const float* __restrict__ beta) {
    int idx = blockIdx.x * blockDim.x + threadIdx.x;   // over B*T*F
    if (idx >= B_*T_*Fd_) return;
    int f = idx % Fd_;
    int t = (idx / Fd_) % T_;
    int b = idx / (T_*Fd_);
    float v[C_];
    float s = 0.f;
#pragma unroll
    for (int c = 0; c < C_; ++c) {
        v[c] = x[((b*C_ + c)*T_ + t)*Fd_ + f];
        s += v[c];
    }
    float mu = s * (1.0f/C_);
    float vs = 0.f;
#pragma unroll
    for (int c = 0; c < C_; ++c) { float d = v[c]-mu; vs += d*d; }
    float inv = rsqrtf(vs*(1.0f/C_) + 1e-8f);
#pragma unroll
    for (int c = 0; c < C_; ++c) {
        g_xn[((b*C_ + c)*T_ + t)*Fd_ + f] = gamma[c]*(v[c]-mu)*inv + beta[c];
    }
}

// ============================ unfold (-> bf16 hi/lo) ============================
__global__ void kunfold() {
    int idx = blockIdx.x * blockDim.x + threadIdx.x;   // over M_*CK_
    if (idx >= M_*CK_) return;
    int ck = idx & 511;
    int m  = idx >> 9;
    int n  = m % N_;
    int l  = m / N_;
    int c  = ck >> 3, k = ck & 7;
    int b  = n >> 7, t = n & 127;
    float v = g_xn[((b*C_ + c)*T_ + t)*Fd_ + (l + k)];
    split_store(g_h0h, g_h0l, idx, v);
}

// ============ weight transpose + bf16 split: W (R x Cc) -> Bt (Cc x R) ============
__global__ void ktrans(const float* __restrict__ W, __nv_bfloat16* __restrict__ bh,
                       __nv_bfloat16* __restrict__ bl, int R, int Cc) {
    __shared__ float t[32][33];
    int c0 = blockIdx.x*32;
    int r0 = blockIdx.y*32;
    int tx = threadIdx.x, ty = threadIdx.y;
#pragma unroll
    for (int i = 0; i < 4; ++i)
        t[ty + i*8][tx] = W[(size_t)(r0 + ty + i*8)*Cc + c0 + tx];
    __syncthreads();
#pragma unroll
    for (int i = 0; i < 4; ++i) {
        int n = c0 + ty + i*8;
        int k = r0 + tx;
        split_store(bh, bl, (size_t)n*R + k, t[tx][ty + i*8]);
    }
}

// ============================ mma.sync split-bf16 GEMM ============================
// C(M x N) = A(M x K) * B(K x N);  A: hi/lo bf16 row-major [M][K],
// B: hi/lo bf16 transposed [N][K].  CTA tile 128x128, warp tile 32x64, BK=32.
// SMEM stage layout: AH | AL | BH | BL, each 128 rows x 80B (64B data + 16B pad).
#define ROWB   80
#define MATB   (128*ROWB)          // 10240
#define STAGEB (4*MATB)            // 40960
#define NSTAGE 3
#define GEMM_DSMEM (NSTAGE*STAGEB)

__device__ __forceinline__ void load_stage(uint32_t sb, int k0,
    const __nv_bfloat16* __restrict__ Ah, const __nv_bfloat16* __restrict__ Al,
    const __nv_bfloat16* __restrict__ Bh, const __nv_bfloat16* __restrict__ Bl,
    int K, int bm, int bn, int tid) {
#pragma unroll
    for (int i = tid; i < 512; i += 256) {
        int row = i >> 2, ch = i & 3;
        uint32_t so = (uint32_t)(row*ROWB + ch*16);
        size_t ga = (size_t)(bm + row)*K + k0 + ch*8;
        size_t gb = (size_t)(bn + row)*K + k0 + ch*8;
        cp16(sb + 0*MATB + so, Ah + ga);
        cp16(sb + 1*MATB + so, Al + ga);
        cp16(sb + 2*MATB + so, Bh + gb);
        cp16(sb + 3*MATB + so, Bl + gb);
    }
}

__global__ __launch_bounds__(256) void kgemm(
    const __nv_bfloat16* __restrict__ Ah, const __nv_bfloat16* __restrict__ Al,
    const __nv_bfloat16* __restrict__ Bh, const __nv_bfloat16* __restrict__ Bl,
    float* __restrict__ U, int K, int Nld) {
    extern __shared__ char dsm[];
    uint32_t dyn = smem_u32(dsm);
    int tid  = threadIdx.x;
    int wid  = tid >> 5, lane = tid & 31;
    int bm   = blockIdx.y * 128, bn = blockIdx.x * 128;
    int wm   = (wid >> 1) * 32;        // warp m offset (0,32,64,96)
    int wn   = (wid & 1)  * 64;        // warp n offset (0,64)

    // per-lane ldmatrix row/chunk selectors
    int g = lane >> 3;
    int lrow = (g & 1) * 8 + (lane & 7);   // row within 16-row tile
    int lsel = g >> 1;                      // k-chunk half within k16

    float acc[2][8][4];
#pragma unroll
    for (int i = 0; i < 2; ++i)
#pragma unroll
        for (int j = 0; j < 8; ++j)
#pragma unroll
            for (int q = 0; q < 4; ++q) acc[i][j][q] = 0.f;

    int nc = K >> 5;                    // chunks of 32
    // prologue: fill pipeline
#pragma unroll
    for (int s = 0; s < NSTAGE; ++s) {
        if (s < nc) load_stage(dyn + s*STAGEB, s*32, Ah, Al, Bh, Bl, K, bm, bn, tid);
        CP_COMMIT();
    }

    for (int c = 0; c < nc; ++c) {
        asm volatile("cp.async.wait_group %0;" :: "n"(NSTAGE - 1) : "memory");
        __syncthreads();
        uint32_t sb = dyn + (c % NSTAGE)*STAGEB;
#pragma unroll
        for (int kk = 0; kk < 2; ++kk) {
            uint32_t chOff = (uint32_t)((kk*2 + lsel)*16);
            uint32_t ah[2][4], al[2][4], bh[4][4], bl[4][4];
#pragma unroll
            for (int i = 0; i < 2; ++i) {
                uint32_t ro = (uint32_t)((wm + i*16 + lrow)*ROWB) + chOff;
                ldsm4(ah[i], sb + 0*MATB + ro);
                ldsm4(al[i], sb + 1*MATB + ro);
            }
#pragma unroll
            for (int j16 = 0; j16 < 4; ++j16) {
                uint32_t ro = (uint32_t)((wn + j16*16 + lrow)*ROWB) + chOff;
                ldsm4(bh[j16], sb + 2*MATB + ro);
                ldsm4(bl[j16], sb + 3*MATB + ro);
            }
#pragma unroll
            for (int i = 0; i < 2; ++i)
#pragma unroll
                for (int j = 0; j < 8; ++j) {
                    int j16 = j >> 1, hf = j & 1;
                    hmma(acc[i][j], ah[i], bh[j16][hf], bh[j16][2 + hf]);
                    hmma(acc[i][j], ah[i], bl[j16][hf], bl[j16][2 + hf]);
                    hmma(acc[i][j], al[i], bh[j16][hf], bh[j16][2 + hf]);
                }
        }
        __syncthreads();
        int nx = c + NSTAGE;
        if (nx < nc) load_stage(dyn + (c % NSTAGE)*STAGEB, nx*32, Ah, Al, Bh, Bl, K, bm, bn, tid);
        CP_COMMIT();
    }

    // epilogue: direct stores (float2 per acc pair)
    int qrow = lane >> 2;          // 0..7
    int qcol = (lane & 3) * 2;
#pragma unroll
    for (int i = 0; i < 2; ++i) {
        int r0 = bm + wm + i*16 + qrow;
#pragma unroll
        for (int j = 0; j < 8; ++j) {
            int cc = bn + wn + j*8 + qcol;
            *(float2*)&U[(size_t)r0*Nld + cc]       = make_float2(acc[i][j][0], acc[i][j][1]);
            *(float2*)&U[(size_t)(r0 + 8)*Nld + cc] = make_float2(acc[i][j][2], acc[i][j][3]);
        }
    }
}

// ============================ SRU scan (-> bf16 hi/lo h) ============================
__global__ void kscan(const float* __restrict__ U,
                      __nv_bfloat16* __restrict__ hh, __nv_bfloat16* __restrict__ hl,
                      const float* __restrict__ bf, const float* __restrict__ br) {
    int n   = blockIdx.x;
    int dir = blockIdx.y;
    int h   = threadIdx.x;
    int base = dir * (4*H_) + h;
    float bfv = bf[dir*H_ + h];
    float brv = br[dir*H_ + h];
    int l    = dir ? (L_ - 1) : 0;
    int step = dir ? -1 : 1;
    float c = 0.f;

    size_t ro = ((size_t)(l * N_ + n)) * (8*H_) + base;
    float z  = U[ro];
    float fv = U[ro + H_];
    float rv = U[ro + 2*H_];
    float hp = U[ro + 3*H_];

    for (int it = 0; it < L_; ++it) {
        int lcur = l;
        int lnext = l + step;
        float zn = 0.f, fn = 0.f, rn = 0.f, hpn = 0.f;
        if (it + 1 < L_) {
            size_t ro2 = ((size_t)(lnext * N_ + n)) * (8*H_) + base;
            zn  = U[ro2];
            fn  = U[ro2 + H_];
            rn  = U[ro2 + 2*H_];
            hpn = U[ro2 + 3*H_];
        }
        float ff = 1.f / (1.f + __expf(-(fv + bfv)));
        float rr = 1.f / (1.f + __expf(-(rv + brv)));
        c = ff * c + (1.f - ff) * z;
        float o = rr * c + (1.f - rr) * hp;
        split_store(hh, hl, ((size_t)(lcur * N_ + n)) * (2*H_) + dir*H_ + h, o);
        z = zn; fv = fn; rv = rn; hp = hpn;
        l = lnext;
    }
}

// ============================ conv-transpose gather + residual ============================
#define TFO 16
__global__ void kfinal(const float* __restrict__ Y, const float* __restrict__ convb,
                       float* __restrict__ out) {
    __shared__ float sh[23 * 513];
    int n   = blockIdx.x;
    int fob = blockIdx.y * TFO;
    int tid = threadIdx.x;
    for (int i = tid; i < 23 * 512; i += 256) {
        int r = i >> 9, col = i & 511;
        int l = fob - 7 + r;
        float v = 0.f;
        if (l >= 0 && l < L_) v = Y[((size_t)(l * N_ + n)) * 512 + col];
        sh[r * 513 + col] = v;
    }
    __syncthreads();
    int fo_local = tid & 15;
    int cg = tid >> 4;
    int fo = fob + fo_local;
    int b = n >> 7, t = n & 127;
#pragma unroll
    for (int cc = 0; cc < 4; ++cc) {
        int c = cg * 4 + cc;
        float acc = convb[c];
#pragma unroll
        for (int k = 0; k < 8; ++k)
            acc += sh[(fo_local + 7 - k) * 513 + c * 8 + k];
        int oi = ((b*C_ + c)*T_ + t)*Fd_ + fo;
        out[oi] = acc + g_xn[oi];
    }
}

// ============================ launch ============================
extern "C" void kernel_launch(void* const* d_in, const int* in_sizes, int n_in,
                              void* d_out, int out_size) {
    const float* x     = (const float*)d_in[0];
    const float* gamma = (const float*)d_in[1];
    const float* beta  = (const float*)d_in[2];
    const float* W[4]  = {(const float*)d_in[3],  (const float*)d_in[6],
                          (const float*)d_in[9],  (const float*)d_in[12]};
    const float* bf[4] = {(const float*)d_in[4],  (const float*)d_in[7],
                          (const float*)d_in[10], (const float*)d_in[13]};
    const float* br[4] = {(const float*)d_in[5],  (const float*)d_in[8],
                          (const float*)d_in[11], (const float*)d_in[14]};
    const float* convW = (const float*)d_in[15];   // (2H, C, K) == (256, 512) row-major
    const float* convb = (const float*)d_in[16];
    float* out = (float*)d_out;

    void *pU, *ph0h, *ph0l, *phh, *phl, *pbh, *pbl;
    cudaGetSymbolAddress(&pU,   g_U);
    cudaGetSymbolAddress(&ph0h, g_h0h);
    cudaGetSymbolAddress(&ph0l, g_h0l);
    cudaGetSymbolAddress(&phh,  g_hh);
    cudaGetSymbolAddress(&phl,  g_hl);
    cudaGetSymbolAddress(&pbh,  g_Bth);
    cudaGetSymbolAddress(&pbl,  g_Btl);
    __nv_bfloat16* Bth = (__nv_bfloat16*)pbh;
    __nv_bfloat16* Btl = (__nv_bfloat16*)pbl;
    const int woff[5] = {WOFF0, WOFF1, WOFF2, WOFF3, WOFFC};

    cudaFuncSetAttribute(kgemm, cudaFuncAttributeMaxDynamicSharedMemorySize, GEMM_DSMEM);

    knorm<<<(B_*T_*Fd_ + 255)/256, 256>>>(x, gamma, beta);
    kunfold<<<(M_*CK_ + 255)/256, 256>>>();

    // transpose + split weights: W0 (512x1024), W1-3 (256x1024), convW (256x512)
    ktrans<<<dim3(1024/32, 512/32), dim3(32,8)>>>(W[0], Bth + woff[0], Btl + woff[0], 512, 1024);
    for (int i = 1; i < 4; ++i)
        ktrans<<<dim3(1024/32, 256/32), dim3(32,8)>>>(W[i], Bth + woff[i], Btl + woff[i], 256, 1024);
    ktrans<<<dim3(512/32, 256/32), dim3(32,8)>>>(convW, Bth + woff[4], Btl + woff[4], 256, 512);

    // layer 0: A = h0 (M x 512), N = 1024
    kgemm<<<dim3(1024/128, M_/128), 256, GEMM_DSMEM>>>(
        (const __nv_bfloat16*)ph0h, (const __nv_bfloat16*)ph0l,
        Bth + woff[0], Btl + woff[0], (float*)pU, 512, 1024);
    kscan<<<dim3(N_, 2), 128>>>((const float*)pU, (__nv_bfloat16*)phh, (__nv_bfloat16*)phl,
                                bf[0], br[0]);

    for (int i = 1; i < 4; ++i) {
        kgemm<<<dim3(1024/128, M_/128), 256, GEMM_DSMEM>>>(
            (const __nv_bfloat16*)phh, (const __nv_bfloat16*)phl,
            Bth + woff[i], Btl + woff[i], (float*)pU, 256, 1024);
        kscan<<<dim3(N_, 2), 128>>>((const float*)pU, (__nv_bfloat16*)phh, (__nv_bfloat16*)phl,
                                    bf[i], br[i]);
    }

    // conv-transpose as GEMM: Y (M x 512) = h (M x 256) @ convW^T-layout (512 x 256)
    kgemm<<<dim3(512/128, M_/128), 256, GEMM_DSMEM>>>(
        (const __nv_bfloat16*)phh, (const __nv_bfloat16*)phl,
        Bth + woff[4], Btl + woff[4], (float*)pU, 256, 512);
    kfinal<<<dim3(N_, Fd_/TFO), 256>>>((const float*)pU, convb, out);
}

// round 8
// speedup vs baseline: 2.0489x; 1.0550x over previous
#include <cuda_runtime.h>
#include <cuda_bf16.h>
#include <math.h>
#include <stdint.h>

#define B_  4
#define C_  64
#define T_  128
#define Fd_ 128
#define H_  128
#define K_  8
#define L_  121              // F - K + 1
#define N_  (B_*T_)          // 512
#define M_  (L_*N_)          // 61952
#define CK_ (C_*K_)          // 512

// weight scratch offsets (elements) for transposed bf16 hi/lo weights [N][K]
#define WOFF0 0
#define WOFF1 (1024*512)
#define WOFF2 (WOFF1 + 1024*256)
#define WOFF3 (WOFF2 + 1024*256)
#define WOFFC (WOFF3 + 1024*256)
#define WTOT  (WOFFC + 512*256)

// ---- scratch (device globals; no allocation allowed) ----
__device__ float         g_xn [B_*C_*T_*Fd_];   // 16.8 MB  normed input (fp32, for residual)
__device__ __nv_bfloat16 g_h0h[M_*CK_];         // 63.4 MB  unfolded input hi
__device__ __nv_bfloat16 g_h0l[M_*CK_];         // 63.4 MB  unfolded input lo
__device__ __nv_bfloat16 g_hh [M_*2*H_];        // 31.7 MB  layer output hi
__device__ __nv_bfloat16 g_hl [M_*2*H_];        // 31.7 MB  layer output lo
__device__ float         g_U  [M_*8*H_];        // 253.8 MB GEMM output (fp32)
__device__ __nv_bfloat16 g_Bth[WTOT];           // transposed weights hi
__device__ __nv_bfloat16 g_Btl[WTOT];           // transposed weights lo

// ============================ helpers ============================
__device__ __forceinline__ uint32_t smem_u32(const void* p) {
    uint32_t a;
    asm("{ .reg .u64 t; cvta.to.shared.u64 t, %1; cvt.u32.u64 %0, t; }" : "=r"(a) : "l"(p));
    return a;
}
__device__ __forceinline__ void cp16(uint32_t s, const void* g) {
    asm volatile("cp.async.cg.shared.global [%0], [%1], 16;" :: "r"(s), "l"(g) : "memory");
}
#define CP_COMMIT() asm volatile("cp.async.commit_group;" ::: "memory")

__device__ __forceinline__ void ldsm4(uint32_t* r, uint32_t addr) {
    asm volatile("ldmatrix.sync.aligned.m8n8.x4.shared.b16 {%0,%1,%2,%3}, [%4];"
        : "=r"(r[0]), "=r"(r[1]), "=r"(r[2]), "=r"(r[3]) : "r"(addr));
}
__device__ __forceinline__ void hmma(float* c, const uint32_t* a, uint32_t b0, uint32_t b1) {
    asm volatile("mma.sync.aligned.m16n8k16.row.col.f32.bf16.bf16.f32 "
        "{%0,%1,%2,%3}, {%4,%5,%6,%7}, {%8,%9}, {%0,%1,%2,%3};"
        : "+f"(c[0]), "+f"(c[1]), "+f"(c[2]), "+f"(c[3])
        : "r"(a[0]), "r"(a[1]), "r"(a[2]), "r"(a[3]), "r"(b0), "r"(b1));
}

__device__ __forceinline__ void split_store(__nv_bfloat16* ph, __nv_bfloat16* pl,
                                            size_t idx, float v) {
    __nv_bfloat16 h = __float2bfloat16(v);
    ph[idx] = h;
    pl[idx] = __float2bfloat16(v - __bfloat162float(h));
}

// ============================ channel norm ============================
__global__ void knorm(const float* __restrict__ x, const float* __restrict__ gamma,
                      const float* __restrict__ beta) {
    int idx = blockIdx.x * blockDim.x + threadIdx.x;   // over B*T*F
    if (idx >= B_*T_*Fd_) return;
    int f = idx % Fd_;
    int t = (idx / Fd_) % T_;
    int b = idx / (T_*Fd_);
    float v[C_];
    float s = 0.f;
#pragma unroll
    for (int c = 0; c < C_; ++c) {
        v[c] = x[((b*C_ + c)*T_ + t)*Fd_ + f];
        s += v[c];
    }
    float mu = s * (1.0f/C_);
    float vs = 0.f;
#pragma unroll
    for (int c = 0; c < C_; ++c) { float d = v[c]-mu; vs += d*d; }
    float inv = rsqrtf(vs*(1.0f/C_) + 1e-8f);
#pragma unroll
    for (int c = 0; c < C_; ++c) {
        g_xn[((b*C_ + c)*T_ + t)*Fd_ + f] = gamma[c]*(v[c]-mu)*inv + beta[c];
    }
}

// ============================ unfold (-> bf16 hi/lo) ============================
__global__ void kunfold() {
    int idx = blockIdx.x * blockDim.x + threadIdx.x;   // over M_*CK_
    if (idx >= M_*CK_) return;
    int ck = idx & 511;
    int m  = idx >> 9;
    int n  = m % N_;
    int l  = m / N_;
    int c  = ck >> 3, k = ck & 7;
    int b  = n >> 7, t = n & 127;
    float v = g_xn[((b*C_ + c)*T_ + t)*Fd_ + (l + k)];
    split_store(g_h0h, g_h0l, idx, v);
}

// ============ weight transpose + bf16 split: W (R x Cc) -> Bt (Cc x R) ============
__global__ void ktrans(const float* __restrict__ W, __nv_bfloat16* __restrict__ bh,
                       __nv_bfloat16* __restrict__ bl, int R, int Cc) {
    __shared__ float t[32][33];
    int c0 = blockIdx.x*32;
    int r0 = blockIdx.y*32;
    int tx = threadIdx.x, ty = threadIdx.y;
#pragma unroll
    for (int i = 0; i < 4; ++i)
        t[ty + i*8][tx] = W[(size_t)(r0 + ty + i*8)*Cc + c0 + tx];
    __syncthreads();
#pragma unroll
    for (int i = 0; i < 4; ++i) {
        int n = c0 + ty + i*8;
        int k = r0 + tx;
        split_store(bh, bl, (size_t)n*R + k, t[tx][ty + i*8]);
    }
}

// ============================ mma.sync split-bf16 GEMM ============================
// C(M x N) = A(M x K) * B(K x N);  A: hi/lo bf16 row-major [M][K],
// B: hi/lo bf16 transposed [N][K].  CTA tile 256x128, warp tile 64x64, BK=32.
// SMEM stage: AH(256x80) | AL(256x80) | BH(128x80) | BL(128x80); rows 80B = 64B + 16 pad.
#define ROWB   80
#define A_MATB (256*ROWB)          // 20480
#define B_MATB (128*ROWB)          // 10240
#define SB_AH  0
#define SB_AL  A_MATB
#define SB_BH  (2*A_MATB)
#define SB_BL  (2*A_MATB + B_MATB)
#define STAGEB (2*A_MATB + 2*B_MATB)   // 61440
#define NSTAGE 3
#define GEMM_DSMEM (NSTAGE*STAGEB)     // 184320

__device__ __forceinline__ void load_stage(uint32_t sb, int k0,
    const __nv_bfloat16* __restrict__ Ah, const __nv_bfloat16* __restrict__ Al,
    const __nv_bfloat16* __restrict__ Bh, const __nv_bfloat16* __restrict__ Bl,
    int K, int bm, int bn, int tid) {
    // A: 256 rows x 4 chunks = 1024 cp16 each for hi/lo -> 4 per thread each
#pragma unroll
    for (int i = tid; i < 1024; i += 256) {
        int row = i >> 2, ch = i & 3;
        uint32_t so = (uint32_t)(row*ROWB + ch*16);
        size_t ga = (size_t)(bm + row)*K + k0 + ch*8;
        cp16(sb + SB_AH + so, Ah + ga);
        cp16(sb + SB_AL + so, Al + ga);
    }
    // B: 128 rows x 4 chunks = 512 cp16 each for hi/lo -> 2 per thread each
#pragma unroll
    for (int i = tid; i < 512; i += 256) {
        int row = i >> 2, ch = i & 3;
        uint32_t so = (uint32_t)(row*ROWB + ch*16);
        size_t gb = (size_t)(bn + row)*K + k0 + ch*8;
        cp16(sb + SB_BH + so, Bh + gb);
        cp16(sb + SB_BL + so, Bl + gb);
    }
}

__global__ __launch_bounds__(256) void kgemm(
    const __nv_bfloat16* __restrict__ Ah, const __nv_bfloat16* __restrict__ Al,
    const __nv_bfloat16* __restrict__ Bh, const __nv_bfloat16* __restrict__ Bl,
    float* __restrict__ U, int K, int Nld) {
    extern __shared__ char dsm[];
    uint32_t dyn = smem_u32(dsm);
    int tid  = threadIdx.x;
    int wid  = tid >> 5, lane = tid & 31;
    int bm   = blockIdx.y * 256, bn = blockIdx.x * 128;
    int wm   = (wid >> 1) * 64;        // warp m offset (0,64,128,192)
    int wn   = (wid & 1)  * 64;        // warp n offset (0,64)

    // per-lane ldmatrix row/chunk selectors
    int g = lane >> 3;
    int lrow = (g & 1) * 8 + (lane & 7);   // row within 16-row tile
    int lsel = g >> 1;                      // k-chunk half within k16

    float acc[4][8][4];
#pragma unroll
    for (int i = 0; i < 4; ++i)
#pragma unroll
        for (int j = 0; j < 8; ++j)
#pragma unroll
            for (int q = 0; q < 4; ++q) acc[i][j][q] = 0.f;

    int nc = K >> 5;                    // chunks of 32
    // prologue: fill NSTAGE-1 stages
#pragma unroll
    for (int s = 0; s < NSTAGE - 1; ++s) {
        load_stage(dyn + s*STAGEB, s*32, Ah, Al, Bh, Bl, K, bm, bn, tid);
        CP_COMMIT();
    }

    for (int c = 0; c < nc; ++c) {
        asm volatile("cp.async.wait_group %0;" :: "n"(NSTAGE - 2) : "memory");
        __syncthreads();
        // issue next stage loads BEFORE compute (into the slot consumed last iter)
        int nx = c + NSTAGE - 1;
        if (nx < nc)
            load_stage(dyn + (nx % NSTAGE)*STAGEB, nx*32, Ah, Al, Bh, Bl, K, bm, bn, tid);
        CP_COMMIT();

        uint32_t sb = dyn + (c % NSTAGE)*STAGEB;
#pragma unroll
        for (int kk = 0; kk < 2; ++kk) {
            uint32_t chOff = (uint32_t)((kk*2 + lsel)*16);
            uint32_t ah[4][4], al[4][4], bh[4][4], bl[4][4];
#pragma unroll
            for (int i = 0; i < 4; ++i) {
                uint32_t ro = (uint32_t)((wm + i*16 + lrow)*ROWB) + chOff;
                ldsm4(ah[i], sb + SB_AH + ro);
                ldsm4(al[i], sb + SB_AL + ro);
            }
#pragma unroll
            for (int j16 = 0; j16 < 4; ++j16) {
                uint32_t ro = (uint32_t)((wn + j16*16 + lrow)*ROWB) + chOff;
                ldsm4(bh[j16], sb + SB_BH + ro);
                ldsm4(bl[j16], sb + SB_BL + ro);
            }
#pragma unroll
            for (int i = 0; i < 4; ++i)
#pragma unroll
                for (int j = 0; j < 8; ++j) {
                    int j16 = j >> 1, hf = j & 1;
                    hmma(acc[i][j], ah[i], bh[j16][hf], bh[j16][2 + hf]);
                    hmma(acc[i][j], ah[i], bl[j16][hf], bl[j16][2 + hf]);
                    hmma(acc[i][j], al[i], bh[j16][hf], bh[j16][2 + hf]);
                }
        }
        __syncthreads();
    }

    // epilogue: direct stores (float2 per acc pair)
    int qrow = lane >> 2;          // 0..7
    int qcol = (lane & 3) * 2;
#pragma unroll
    for (int i = 0; i < 4; ++i) {
        int r0 = bm + wm + i*16 + qrow;
#pragma unroll
        for (int j = 0; j < 8; ++j) {
            int cc = bn + wn + j*8 + qcol;
            *(float2*)&U[(size_t)r0*Nld + cc]       = make_float2(acc[i][j][0], acc[i][j][1]);
            *(float2*)&U[(size_t)(r0 + 8)*Nld + cc] = make_float2(acc[i][j][2], acc[i][j][3]);
        }
    }
}

// ============================ SRU scan (-> bf16 hi/lo h) ============================
__global__ void kscan(const float* __restrict__ U,
                      __nv_bfloat16* __restrict__ hh, __nv_bfloat16* __restrict__ hl,
                      const float* __restrict__ bf, const float* __restrict__ br) {
    int n   = blockIdx.x;
    int dir = blockIdx.y;
    int h   = threadIdx.x;
    int base = dir * (4*H_) + h;
    float bfv = bf[dir*H_ + h];
    float brv = br[dir*H_ + h];
    int l    = dir ? (L_ - 1) : 0;
    int step = dir ? -1 : 1;
    float c = 0.f;

    size_t ro = ((size_t)(l * N_ + n)) * (8*H_) + base;
    float z  = U[ro];
    float fv = U[ro + H_];
    float rv = U[ro + 2*H_];
    float hp = U[ro + 3*H_];

    for (int it = 0; it < L_; ++it) {
        int lcur = l;
        int lnext = l + step;
        float zn = 0.f, fn = 0.f, rn = 0.f, hpn = 0.f;
        if (it + 1 < L_) {
            size_t ro2 = ((size_t)(lnext * N_ + n)) * (8*H_) + base;
            zn  = U[ro2];
            fn  = U[ro2 + H_];
            rn  = U[ro2 + 2*H_];
            hpn = U[ro2 + 3*H_];
        }
        float ff = 1.f / (1.f + __expf(-(fv + bfv)));
        float rr = 1.f / (1.f + __expf(-(rv + brv)));
        c = ff * c + (1.f - ff) * z;
        float o = rr * c + (1.f - rr) * hp;
        split_store(hh, hl, ((size_t)(lcur * N_ + n)) * (2*H_) + dir*H_ + h, o);
        z = zn; fv = fn; rv = rn; hp = hpn;
        l = lnext;
    }
}

// ============================ conv-transpose gather + residual ============================
#define TFO 16
__global__ void kfinal(const float* __restrict__ Y, const float* __restrict__ convb,
                       float* __restrict__ out) {
    __shared__ float sh[23 * 513];
    int n   = blockIdx.x;
    int fob = blockIdx.y * TFO;
    int tid = threadIdx.x;
    for (int i = tid; i < 23 * 512; i += 256) {
        int r = i >> 9, col = i & 511;
        int l = fob - 7 + r;
        float v = 0.f;
        if (l >= 0 && l < L_) v = Y[((size_t)(l * N_ + n)) * 512 + col];
        sh[r * 513 + col] = v;
    }
    __syncthreads();
    int fo_local = tid & 15;
    int cg = tid >> 4;
    int fo = fob + fo_local;
    int b = n >> 7, t = n & 127;
#pragma unroll
    for (int cc = 0; cc < 4; ++cc) {
        int c = cg * 4 + cc;
        float acc = convb[c];
#pragma unroll
        for (int k = 0; k < 8; ++k)
            acc += sh[(fo_local + 7 - k) * 513 + c * 8 + k];
        int oi = ((b*C_ + c)*T_ + t)*Fd_ + fo;
        out[oi] = acc + g_xn[oi];
    }
}

// ============================ launch ============================
extern "C" void kernel_launch(void* const* d_in, const int* in_sizes, int n_in,
                              void* d_out, int out_size) {
    const float* x     = (const float*)d_in[0];
    const float* gamma = (const float*)d_in[1];
    const float* beta  = (const float*)d_in[2];
    const float* W[4]  = {(const float*)d_in[3],  (const float*)d_in[6],
                          (const float*)d_in[9],  (const float*)d_in[12]};
    const float* bf[4] = {(const float*)d_in[4],  (const float*)d_in[7],
                          (const float*)d_in[10], (const float*)d_in[13]};
    const float* br[4] = {(const float*)d_in[5],  (const float*)d_in[8],
                          (const float*)d_in[11], (const float*)d_in[14]};
    const float* convW = (const float*)d_in[15];   // (2H, C, K) == (256, 512) row-major
    const float* convb = (const float*)d_in[16];
    float* out = (float*)d_out;

    void *pU, *ph0h, *ph0l, *phh, *phl, *pbh, *pbl;
    cudaGetSymbolAddress(&pU,   g_U);
    cudaGetSymbolAddress(&ph0h, g_h0h);
    cudaGetSymbolAddress(&ph0l, g_h0l);
    cudaGetSymbolAddress(&phh,  g_hh);
    cudaGetSymbolAddress(&phl,  g_hl);
    cudaGetSymbolAddress(&pbh,  g_Bth);
    cudaGetSymbolAddress(&pbl,  g_Btl);
    __nv_bfloat16* Bth = (__nv_bfloat16*)pbh;
    __nv_bfloat16* Btl = (__nv_bfloat16*)pbl;
    const int woff[5] = {WOFF0, WOFF1, WOFF2, WOFF3, WOFFC};

    cudaFuncSetAttribute(kgemm, cudaFuncAttributeMaxDynamicSharedMemorySize, GEMM_DSMEM);

    knorm<<<(B_*T_*Fd_ + 255)/256, 256>>>(x, gamma, beta);
    kunfold<<<(M_*CK_ + 255)/256, 256>>>();

    // transpose + split weights: W0 (512x1024), W1-3 (256x1024), convW (256x512)
    ktrans<<<dim3(1024/32, 512/32), dim3(32,8)>>>(W[0], Bth + woff[0], Btl + woff[0], 512, 1024);
    for (int i = 1; i < 4; ++i)
        ktrans<<<dim3(1024/32, 256/32), dim3(32,8)>>>(W[i], Bth + woff[i], Btl + woff[i], 256, 1024);
    ktrans<<<dim3(512/32, 256/32), dim3(32,8)>>>(convW, Bth + woff[4], Btl + woff[4], 256, 512);

    // layer 0: A = h0 (M x 512), N = 1024
    kgemm<<<dim3(1024/128, M_/256), 256, GEMM_DSMEM>>>(
        (const __nv_bfloat16*)ph0h, (const __nv_bfloat16*)ph0l,
        Bth + woff[0], Btl + woff[0], (float*)pU, 512, 1024);
    kscan<<<dim3(N_, 2), 128>>>((const float*)pU, (__nv_bfloat16*)phh, (__nv_bfloat16*)phl,
                                bf[0], br[0]);

    for (int i = 1; i < 4; ++i) {
        kgemm<<<dim3(1024/128, M_/256), 256, GEMM_DSMEM>>>(
            (const __nv_bfloat16*)phh, (const __nv_bfloat16*)phl,
            Bth + woff[i], Btl + woff[i], (float*)pU, 256, 1024);
        kscan<<<dim3(N_, 2), 128>>>((const float*)pU, (__nv_bfloat16*)phh, (__nv_bfloat16*)phl,
                                    bf[i], br[i]);
    }

    // conv-transpose as GEMM: Y (M x 512) = h (M x 256) @ convW^T-layout (512 x 256)
    kgemm<<<dim3(512/128, M_/256), 256, GEMM_DSMEM>>>(
        (const __nv_bfloat16*)phh, (const __nv_bfloat16*)phl,
        Bth + woff[4], Btl + woff[4], (float*)pU, 256, 512);
    kfinal<<<dim3(N_, Fd_/TFO), 256>>>((const float*)pU, convb, out);
}